// round 6
// baseline (speedup 1.0000x reference)
#include <cuda_runtime.h>
#include <math.h>

#define B 32
#define D 256
#define NN 10000
#define H_ATTN 500
#define H_MLP 1024
#define ALPHA 0.2f

// ---------------- scratch (device globals; zero-initialized at load) ------
__device__ float g_acc_state[B*D];   // split-K partials (zeroed in K2)
__device__ float g_state[B*D];
__device__ float g_sq[B*D];          // tanh(state)*q
__device__ float g_gate[B*D];        // final sigmoid'd gate
__device__ float g_t1[B*H_MLP];      // final relu'd t1
__device__ float g_gf[B*D];
__device__ float g_q[D];
__device__ float g_u[B*D];           // unnormalized sum_n w*emb (zeroed in K2)
__device__ float g_S[B];             // sum_n w (zeroed in K2)
__device__ float g_c0;

__device__ __forceinline__ float sigmoidf_(float x){ return 1.f/(1.f+__expf(-x)); }

// ============ K1: grid 76 x 256
//  u<24 : state partials (seg=u>>2 of 6 feature segs, bgroup=u&3 of 8 b), atomics
//  u<28 : gate, direct write (K=256 full, fused sigmoid)
//  u<44 : t1, direct write (K=256 full, fused bias+relu)
//  u<76 : q[d] warp dots + c0
__global__ void K1(const float* __restrict__ ehr,  const float* __restrict__ path,
                   const float* __restrict__ W_pf,
                   const float* __restrict__ W_gate,const float* __restrict__ b_gate,
                   const float* __restrict__ W1,   const float* __restrict__ b1,
                   const float* __restrict__ W_s1, const float* __restrict__ W_s2,
                   const float* __restrict__ b_s1, const float* __restrict__ b_s2){
  __shared__ float sf[8][260];
  __shared__ float sw2[512];
  int u = blockIdx.x, t = threadIdx.x;            // 256 threads
  if (u < 44){
    int seg, bg, dq;
    if (u < 24){ seg = u >> 2; bg = u & 3; dq = 0; }
    else if (u < 28){ seg = 1; bg = u - 24; dq = 0; }
    else { int idx = u - 28; seg = 1; bg = idx & 3; dq = idx >> 2; }
    // stage features: rows = 8 b of this bgroup, cols = 256 k
    for (int i = t; i < 2048; i += 256){
      int r = i >> 8, c = i & 255; int b = bg*8 + r;
      float e = ehr[b*D + c], f;
      if (seg == 1) f = e;
      else {
        float p = path[b*D + c];
        if (seg == 0)      f = p;
        else if (seg == 2) f = e*p;
        else if (seg == 3) f = e - p;
        else if (seg == 4) f = p - e;
        else               f = e + p;
      }
      sf[r][c] = f;
    }
    __syncthreads();
    float a0=0.f,a1=0.f,a2=0.f,a3=0.f,a4=0.f,a5=0.f,a6=0.f,a7=0.f;
    const float* Wp;
    int ldw;
    if (u < 24){ Wp = W_pf + (size_t)seg*256*D + t; ldw = D; }
    else if (u < 28){ Wp = W_gate + t; ldw = D; }
    else { Wp = W1 + dq*256 + t; ldw = H_MLP; }
    #pragma unroll 4
    for (int k = 0; k < 256; k++){
      float w = Wp[(size_t)k*ldw];
      a0 += sf[0][k]*w; a1 += sf[1][k]*w; a2 += sf[2][k]*w; a3 += sf[3][k]*w;
      a4 += sf[4][k]*w; a5 += sf[5][k]*w; a6 += sf[6][k]*w; a7 += sf[7][k]*w;
    }
    float acc[8] = {a0,a1,a2,a3,a4,a5,a6,a7};
    if (u < 24){
      #pragma unroll
      for (int r = 0; r < 8; r++) atomicAdd(&g_acc_state[(bg*8+r)*D + t], acc[r]);
    } else if (u < 28){
      float bb = b_gate[t];
      #pragma unroll
      for (int r = 0; r < 8; r++) g_gate[(bg*8+r)*D + t] = sigmoidf_(acc[r] + bb);
    } else {
      int d = dq*256 + t;
      float bb = b1[d];
      #pragma unroll
      for (int r = 0; r < 8; r++) g_t1[(bg*8+r)*H_MLP + d] = fmaxf(acc[r] + bb, 0.f);
    }
  } else {
    // q[d] = W_s1[d,:].W_s2 ; 32 blocks x 8 warps (warp per d)
    for (int i = t; i < 125; i += 256)
      *(float4*)&sw2[i*4] = *(const float4*)(W_s2 + i*4);
    __syncthreads();
    int qb = u - 44, w = t >> 5, lane = t & 31;
    int d = qb*8 + w;
    const float4* row = (const float4*)(W_s1 + d*H_ATTN);   // 2000B rows, 16B aligned
    float s = 0.f;
    #pragma unroll
    for (int i = 0; i < 4; i++){
      int idx = lane + i*32;
      if (idx < 125){
        float4 v = row[idx];
        float4 q = *(const float4*)&sw2[idx*4];
        s += v.x*q.x + v.y*q.y + v.z*q.z + v.w*q.w;
      }
    }
    #pragma unroll
    for (int o = 16; o > 0; o >>= 1) s += __shfl_down_sync(0xffffffffu, s, o);
    if (lane == 0) g_q[d] = s;
    if (qb == 0 && w == 0){
      float c = 0.f;
      for (int h = lane; h < H_ATTN; h += 32) c += b_s1[h]*sw2[h];
      #pragma unroll
      for (int o = 16; o > 0; o >>= 1) c += __shfl_down_sync(0xffffffffu, c, o);
      if (lane == 0) g_c0 = c + b_s2[0];
    }
  }
}

// ============ K2: state activation + sq; zero scratch (grid 32 x 256)
__global__ void K2(const float* __restrict__ b_pf){
  int i = blockIdx.x*256 + threadIdx.x;           // 0..8191
  int d = i & 255;
  float st = tanhf(g_acc_state[i] + b_pf[d]);
  g_state[i] = st;
  g_sq[i]    = st * g_q[d];
  g_acc_state[i] = 0.f;
  g_u[i] = 0.f;
  if (i < B) g_S[i] = 0.f;
}

// ============ K3: [0,313): attention (32 n/block) | [313,345): gf
//  pass1: logit = emb.sq + c0 with double-buffered ssq prefetch
//  w = exp(logit*mask) (no max-shift: masked logits O(1e-3))
//  pass2: u_raw += w.emb ; S += sum w
__global__ void K3(const float* __restrict__ W2, const float* __restrict__ b2,
                   const float* __restrict__ emb, const float* __restrict__ asp){
  __shared__ float smem[11424];   // semb 32*257 | ssq 2*32*33 | sw 32*33 | sS 32
  int bid = blockIdx.x, t = threadIdx.x;          // 256 threads
  if (bid >= 313){
    float* st = smem;                             // [1024]
    int b = bid - 313;
    for (int i = t; i < H_MLP; i += 256) st[i] = g_t1[b*H_MLP + i];
    __syncthreads();
    float a = 0.f;
    #pragma unroll 4
    for (int k = 0; k < H_MLP; k++) a += st[k]*W2[k*D + t];
    g_gf[b*D + t] = fmaxf(a + b2[t], 0.f);
    return;
  }
  float* semb = smem;                             // [32][257]
  float* ssq  = smem + 8224;                      // [2][32][33]
  float* sw   = smem + 10336;                     // [32][33]
  float* sS   = smem + 11392;                     // [32]
  int n0 = bid*32;
  for (int i = t; i < 8192; i += 256){
    int r = i >> 8, c = i & 255; int n = n0 + r;
    semb[r*257 + c] = (n < NN) ? emb[n*D + c] : 0.f;
  }
  for (int i = t; i < 1024; i += 256){
    int b = i >> 5, c = i & 31;
    ssq[b*33 + c] = g_sq[b*D + c];                // dc=0 into buf 0
  }
  if (t < 32) sS[t] = 0.f;
  __syncthreads();

  int nloc = t & 31, bq = t >> 5;                 // 8 warps, 4 b each
  float acc[4] = {0.f, 0.f, 0.f, 0.f};
  for (int dc = 0; dc < 8; dc++){
    int cur = dc & 1;
    if (dc < 7){                                  // prefetch next dc into other buf
      for (int i = t; i < 1024; i += 256){
        int b = i >> 5, c = i & 31;
        ssq[(cur^1)*1056 + b*33 + c] = g_sq[b*D + (dc+1)*32 + c];
      }
    }
    const float* sq0 = ssq + cur*1056 + (bq*4)*33;
    #pragma unroll
    for (int c = 0; c < 32; c++){
      float e = semb[nloc*257 + dc*32 + c];
      acc[0] += e*sq0[c]; acc[1] += e*sq0[33 + c];
      acc[2] += e*sq0[66 + c]; acc[3] += e*sq0[99 + c];
    }
    __syncthreads();
  }
  // exp + block-local S
  int n = n0 + nloc;
  float c0 = g_c0;
  #pragma unroll
  for (int bb = 0; bb < 4; bb++){
    int b = bq*4 + bb;
    float w = 0.f;
    if (n < NN) w = __expf((acc[bb] + c0)*asp[b*NN + n]);
    sw[b*33 + nloc] = w;
    float s = w;
    #pragma unroll
    for (int o = 16; o > 0; o >>= 1) s += __shfl_down_sync(0xffffffffu, s, o);
    if (nloc == 0) atomicAdd(&sS[b], s);
  }
  __syncthreads();
  // pass 2: u_raw += w . emb
  int dl = t & 31, g = t >> 5;
  for (int dc = 0; dc < 8; dc++){
    float a[4] = {0.f, 0.f, 0.f, 0.f};
    #pragma unroll
    for (int j = 0; j < 32; j++){
      float e = semb[j*257 + dc*32 + dl];
      #pragma unroll
      for (int bb = 0; bb < 4; bb++) a[bb] += sw[(g*4+bb)*33 + j]*e;
    }
    #pragma unroll
    for (int bb = 0; bb < 4; bb++)
      atomicAdd(&g_u[(g*4+bb)*D + dc*32 + dl], a[bb]);
  }
  if (t < 32) atomicAdd(&g_S[t], sS[t]);
}

// ============ K4: normalize+highway folded into staging, dual GEMV + blend
// grid 157 x 512 threads, 64 n per block
__global__ void K4(const float* __restrict__ ehr, const float* __restrict__ asp,
                   const float* __restrict__ lvl,
                   const float* __restrict__ W_gl, const float* __restrict__ b_gl,
                   const float* __restrict__ W_lay,const float* __restrict__ b_lay,
                   float* __restrict__ out){
  __shared__ float2 sv[32][130];
  int t = threadIdx.x;                            // 512
  int nloc = t & 63, bq = t >> 6;                 // 8 groups x 4 b
  int n = blockIdx.x*64 + nloc;
  float accL[4], accG[4];
  #pragma unroll
  for (int i = 0; i < 4; i++){ accL[i] = 0.f; accG[i] = 0.f; }
  for (int h = 0; h < 2; h++){
    for (int i = t; i < 4096; i += 512){
      int b = i >> 7, c = i & 127; int idx = b*D + h*128 + c;
      float uu = g_u[idx] / g_S[b];
      float gt = g_gate[idx];
      float hw = g_state[idx]*uu*(1.f - gt) + ehr[idx]*gt;
      sv[b][c] = make_float2(hw, g_gf[idx]);
    }
    __syncthreads();
    if (n < NN){
      #pragma unroll 4
      for (int c = 0; c < 128; c++){
        int d = h*128 + c;
        float wl = W_lay[(size_t)d*NN + n];
        float wg = W_gl [(size_t)d*NN + n];
        #pragma unroll
        for (int bb = 0; bb < 4; bb++){
          float2 v = sv[bq*4 + bb][c];
          accL[bb] += v.x*wl;
          accG[bb] += v.y*wg;
        }
      }
    }
    __syncthreads();
  }
  if (n < NN){
    float bl = b_lay[n], bg = b_gl[n], lm = lvl[n];
    #pragma unroll
    for (int bb = 0; bb < 4; bb++){
      int b = bq*4 + bb;
      float ll = sigmoidf_(accL[bb] + bl);
      float lg = sigmoidf_(accG[bb] + bg);
      out[b*NN + n] = ALPHA*ll*asp[b*NN + n] + (1.f - ALPHA)*lg*lm;
    }
  }
}

// ---------------- launch ----------------
extern "C" void kernel_launch(void* const* d_in, const int* in_sizes, int n_in,
                              void* d_out, int out_size){
  const float* ehr    = (const float*)d_in[0];
  const float* path   = (const float*)d_in[1];
  const float* asp    = (const float*)d_in[2];
  const float* lvl    = (const float*)d_in[3];
  const float* emb    = (const float*)d_in[4];
  const float* W_pf   = (const float*)d_in[5];
  const float* b_pf   = (const float*)d_in[6];
  const float* W_s1   = (const float*)d_in[7];
  const float* b_s1   = (const float*)d_in[8];
  const float* W_s2   = (const float*)d_in[9];
  const float* b_s2   = (const float*)d_in[10];
  const float* W_gate = (const float*)d_in[11];
  const float* b_gate = (const float*)d_in[12];
  const float* W1     = (const float*)d_in[13];
  const float* b1     = (const float*)d_in[14];
  const float* W2     = (const float*)d_in[15];
  const float* b2     = (const float*)d_in[16];
  const float* W_gl   = (const float*)d_in[17];
  const float* b_gl   = (const float*)d_in[18];
  const float* W_lay  = (const float*)d_in[19];
  const float* b_lay  = (const float*)d_in[20];
  float* out = (float*)d_out;

  K1<<<76, 256>>>(ehr, path, W_pf, W_gate, b_gate, W1, b1, W_s1, W_s2, b_s1, b_s2);
  K2<<<32, 256>>>(b_pf);
  K3<<<345, 256>>>(W2, b2, emb, asp);
  K4<<<157, 512>>>(ehr, asp, lvl, W_gl, b_gl, W_lay, b_lay, out);
}